// round 14
// baseline (speedup 1.0000x reference)
#include <cuda_runtime.h>
#include <cuda_bf16.h>
#include <math.h>

typedef unsigned int u32;
typedef unsigned long long u64;

#define Bx 64
#define Tt 512
#define Hh 512
#define Gg 2048
#define TBH (Tt * Bx * Hh)
#define MAT 9216                 // one 64x64 bf16 matrix, 144B row stride
#define BUFB (8 * MAT)           // 8 matrices per chunk buffer (73728 B)
#define SM_TOTAL (3 * BUFB)      // 221184 B (3-stage ring)
#define NTHR 384                 // 8 consumer warps + 4 producer warps (1/SMSP)

// ---------------- device scratch ----------------
__device__ __nv_bfloat16 g_xh[4][TBH], g_xl[4][TBH];      // layer-input splits [t][b][k]
__device__ __nv_bfloat16 g_Wh[4][Hh * Gg], g_Wl[4][Hh * Gg];  // gate-interleaved cols
__device__ __nv_bfloat16 g_Uh[4][Hh * Gg], g_Ul[4][Hh * Gg];  // (col' = j*64 + nn*4 + g)
__device__ __nv_bfloat16 g_hh[4][2][Bx * Hh], g_hl[4][2][Bx * Hh];  // h splits, dbl-buffered
__device__ float g_firsth[Bx * Hh];
__device__ unsigned g_cnt[4];                              // per-group monotonic counters

// ---------------- helpers ----------------
__device__ __forceinline__ u32 smem_u32(const void* p) {
    u32 a;
    asm("{ .reg .u64 t; cvta.to.shared.u64 t, %1; cvt.u32.u64 %0, t; }" : "=r"(a) : "l"(p));
    return a;
}
__device__ __forceinline__ void ldsm4(u32& r0, u32& r1, u32& r2, u32& r3, u32 a) {
    asm volatile("ldmatrix.sync.aligned.m8n8.x4.shared.b16 {%0,%1,%2,%3}, [%4];"
                 : "=r"(r0), "=r"(r1), "=r"(r2), "=r"(r3) : "r"(a));
}
__device__ __forceinline__ void ldsm4t(u32& r0, u32& r1, u32& r2, u32& r3, u32 a) {
    asm volatile("ldmatrix.sync.aligned.m8n8.x4.trans.shared.b16 {%0,%1,%2,%3}, [%4];"
                 : "=r"(r0), "=r"(r1), "=r"(r2), "=r"(r3) : "r"(a));
}
__device__ __forceinline__ void mma_bf16(float* c, const u32* a, const u32* b) {
    asm volatile("mma.sync.aligned.m16n8k16.row.col.f32.bf16.bf16.f32 "
                 "{%0,%1,%2,%3}, {%4,%5,%6,%7}, {%8,%9}, {%0,%1,%2,%3};"
                 : "+f"(c[0]), "+f"(c[1]), "+f"(c[2]), "+f"(c[3])
                 : "r"(a[0]), "r"(a[1]), "r"(a[2]), "r"(a[3]), "r"(b[0]), "r"(b[1]));
}
#define CP16(dst, src) asm volatile("cp.async.cg.shared.global [%0], [%1], 16;" :: "r"(dst), "l"(src) : "memory")
#define CPCOMMIT()     asm volatile("cp.async.commit_group;" ::: "memory")
#define CPWAIT0()      asm volatile("cp.async.wait_group 0;" ::: "memory")
#define CPWAIT1()      asm volatile("cp.async.wait_group 1;" ::: "memory")
#define CPWAIT2()      asm volatile("cp.async.wait_group 2;" ::: "memory")
#define BARS(id)       asm volatile("bar.sync %0, %1;"   :: "r"(id), "n"(NTHR) : "memory")
#define BARA(id)       asm volatile("bar.arrive %0, %1;" :: "r"(id), "n"(NTHR) : "memory")

__device__ __forceinline__ float sigf(float x) { return 1.f / (1.f + __expf(-x)); }
__device__ __forceinline__ u32 ld_rel(const unsigned* p) {
    u32 v;
    asm volatile("ld.relaxed.gpu.global.u32 %0, [%1];" : "=r"(v) : "l"(p));
    return v;
}
__device__ __forceinline__ void split8(float4 f0, float4 f1, uint4& hv, uint4& lv) {
    float f[8] = {f0.x, f0.y, f0.z, f0.w, f1.x, f1.y, f1.z, f1.w};
    __nv_bfloat16 h[8], l[8];
#pragma unroll
    for (int i = 0; i < 8; ++i) {
        h[i] = __float2bfloat16_rn(f[i]);
        l[i] = __float2bfloat16_rn(f[i] - __bfloat162float(h[i]));
    }
    hv = *reinterpret_cast<uint4*>(h);
    lv = *reinterpret_cast<uint4*>(l);
}

// ---------------- prep / init / states ----------------
__global__ void k_init() {
    if (blockIdx.x == 0 && threadIdx.x < 4) g_cnt[threadIdx.x] = 0u;
    int idx = blockIdx.x * 256 + threadIdx.x;  // 32768 uint4 per array
    ((uint4*)g_hh)[idx] = make_uint4(0, 0, 0, 0);
    ((uint4*)g_hl)[idx] = make_uint4(0, 0, 0, 0);
}
__global__ void k_prep(const float* __restrict__ x) {
    int t = blockIdx.x, b = blockIdx.y, i = threadIdx.x;  // 64 threads, 8 cols each
    const float* src = x + ((size_t)b * Tt + t) * Hh + i * 8;
    float4 f0 = __ldg((const float4*)src), f1 = __ldg((const float4*)(src + 4));
    uint4 hv, lv;
    split8(f0, f1, hv, lv);
    size_t o = ((size_t)t * Bx + b) * Hh + i * 8;
    *(uint4*)(&g_xh[0][o]) = hv;
    *(uint4*)(&g_xl[0][o]) = lv;
}
// split W,U for all 4 layers with gate-interleaved columns:
// dst col' = j*64 + nn*4 + g   <- src col g*512 + j*16 + nn
__global__ void k_splitWU(const float* __restrict__ W, const float* __restrict__ U) {
    int bid = blockIdx.x;
    const float* src = (bid < 4096) ? W : U;
    __nv_bfloat16* dh = (bid < 4096) ? &g_Wh[0][0] : &g_Uh[0][0];
    __nv_bfloat16* dl = (bid < 4096) ? &g_Wl[0][0] : &g_Ul[0][0];
    size_t base = ((size_t)(bid & 4095) * 256 + threadIdx.x) * 4;
#pragma unroll
    for (int q = 0; q < 4; ++q) {
        size_t e = base + q;                 // linear over [layer][k][colp]
        int colp = (int)(e & 2047);
        size_t lk = e >> 11;                 // layer*512 + k
        int j = colp >> 6, r = colp & 63;
        int nn = r >> 2, g = r & 3;
        float f = __ldg(src + lk * 2048 + g * 512 + j * 16 + nn);
        __nv_bfloat16 hi = __float2bfloat16_rn(f);
        dh[e] = hi;
        dl[e] = __float2bfloat16_rn(f - __bfloat162float(hi));
    }
}
__global__ void k_states(float* __restrict__ out) {
    int b = blockIdx.x;
    float4 v = ((const float4*)(g_firsth + (size_t)b * Hh))[threadIdx.x];
    size_t base = (size_t)Bx * Tt * Hh;
#pragma unroll
    for (int l = 0; l < 4; ++l)
        ((float4*)(out + base + ((size_t)l * Bx + b) * Hh))[threadIdx.x] = v;
}

// ---------------- wavefront-pipelined fused LSTM (warp-specialized) ----------------
// 128 CTAs = 4 layer-groups x 32. 384 threads: warps 0-7 consumers (4m x 2n,
// R11 geometry), warps 8-11 producers (one per SMSP; all cp.async staging).
// Ring of 3 chunk buffers; named barriers full[s]=1+s / empty[s]=4+s, count 384.
__global__ void __launch_bounds__(NTHR) k_wave(const float* __restrict__ bias,
                                               float* __restrict__ out) {
    extern __shared__ __align__(128) unsigned char sm[];
    u32 sb = smem_u32(sm);
    const int tid = threadIdx.x, w = tid >> 5, lane = tid & 31;
    const int g = blockIdx.x >> 5, j = blockIdx.x & 31;
    const bool consumer = (w < 8);
    const int mw = (w & 3) * 16, nw = ((w >> 2) & 1) * 32;  // consumers: 4m x 2n
    const int p = lane & 3;

    // consumer cell geometry (R11): ni 0..3
    const int rowb = mw + (lane >> 2) + ((p & 1) ? 8 : 0);
    int colv[4];
    float breg[4][4];
#pragma unroll
    for (int ni = 0; ni < 4; ++ni) {
        int nn = (nw >> 2) + ni * 2 + (p >> 1);
        colv[ni] = j * 16 + nn;
#pragma unroll
        for (int q = 0; q < 4; ++q)
            breg[ni][q] = __ldg(bias + g * Gg + q * 512 + colv[ni]);
    }

    const __nv_bfloat16* wh = g_Wh[g];
    const __nv_bfloat16* wl = g_Wl[g];
    const __nv_bfloat16* uh = g_Uh[g];
    const __nv_bfloat16* ul = g_Ul[g];

    const int pt = tid - 256;  // producer linear id 0..127
    float cst[4] = {0.f, 0.f, 0.f, 0.f};

    for (int t = 0; t < Tt; ++t) {
        if (tid == 0) {
            u32 tg = 32u * (u32)t;
            while (ld_rel(&g_cnt[g]) < tg) { }
            if (g > 0) {
                u32 tg2 = 32u * (u32)(t + 1);
                while (ld_rel(&g_cnt[g - 1]) < tg2) { }
            }
            asm volatile("fence.acq_rel.gpu;" ::: "memory");
        }
        __syncthreads();

        const __nv_bfloat16* axh = g_xh[g] + (size_t)t * Bx * Hh;
        const __nv_bfloat16* axl = g_xl[g] + (size_t)t * Bx * Hh;
        const __nv_bfloat16* ahh = g_hh[g][(t & 1) ^ 1];
        const __nv_bfloat16* ahl = g_hl[g][(t & 1) ^ 1];

        if (!consumer) {
            // ---------------- producer path (128 threads, 1 warp/SMSP) ----------------
            auto stage = [&](int ch) {
                u32 base = sb + (ch % 3) * BUFB;
                int co = ch * 64;
#pragma unroll
                for (int it = 0; it < 4; ++it) {
                    int x = it * 128 + pt;
                    int r = x >> 3, c = x & 7;
                    size_t aso = (size_t)r * Hh + co + c * 8;
                    u32 ad = r * 144 + c * 16;
                    CP16(base + ad, axh + aso);
                    CP16(base + MAT + ad, axl + aso);
                    CP16(base + 2 * MAT + ad, ahh + aso);
                    CP16(base + 3 * MAT + ad, ahl + aso);
                    size_t bso = (size_t)(co + r) * Gg + j * 64 + c * 8;
                    CP16(base + 4 * MAT + ad, wh + bso);
                    CP16(base + 5 * MAT + ad, wl + bso);
                    CP16(base + 6 * MAT + ad, uh + bso);
                    CP16(base + 7 * MAT + ad, ul + bso);
                }
            };
            if (t > 0) BARS(4 + 0);
            stage(0); CPCOMMIT();
            if (t > 0) BARS(4 + 1);
            stage(1); CPCOMMIT();
#pragma unroll 1
            for (int ch = 0; ch < 8; ++ch) {
                int nb = ch + 2;
                if (nb < 8) {
                    if (t > 0 || nb > 2) BARS(4 + nb % 3);
                    stage(nb); CPCOMMIT();
                    CPWAIT2();
                } else if (ch == 6) {
                    CPWAIT1();
                } else {
                    CPWAIT0();
                }
                BARA(1 + ch % 3);
            }
        } else {
            // ---------------- consumer path ----------------
            float xres[4] = {0.f, 0.f, 0.f, 0.f};
            if (g > 0) {
#pragma unroll
                for (int ni = 0; ni < 4; ++ni)
                    xres[ni] = __bfloat162float(__ldg(&axh[rowb * Hh + colv[ni]])) +
                               __bfloat162float(__ldg(&axl[rowb * Hh + colv[ni]]));
            }
            float acc[4][4];
#pragma unroll
            for (int a = 0; a < 4; ++a)
#pragma unroll
                for (int q = 0; q < 4; ++q) acc[a][q] = 0.f;

#pragma unroll 1
            for (int ch = 0; ch < 8; ++ch) {
                BARS(1 + ch % 3);
                u32 b0 = sb + (ch % 3) * BUFB;
#pragma unroll
                for (int kk = 0; kk < 4; ++kk) {
                    int k0 = kk * 16;
                    u32 arow = (mw + (lane & 15)) * 144 + (k0 + ((lane >> 4) << 3)) * 2;
                    u32 fxh[4], fxl[4], fhh[4], fhl[4];
                    ldsm4(fxh[0], fxh[1], fxh[2], fxh[3], b0 + arow);
                    ldsm4(fxl[0], fxl[1], fxl[2], fxl[3], b0 + MAT + arow);
                    ldsm4(fhh[0], fhh[1], fhh[2], fhh[3], b0 + 2 * MAT + arow);
                    ldsm4(fhl[0], fhl[1], fhl[2], fhl[3], b0 + 3 * MAT + arow);
                    u32 brow = (k0 + (lane & 7) + ((lane & 8) ? 8 : 0)) * 144 +
                               (nw + ((lane & 16) ? 8 : 0)) * 2;
                    u32 bwh[8], bwl[8], buh[8], bul[8];
                    ldsm4t(bwh[0], bwh[1], bwh[2], bwh[3], b0 + 4 * MAT + brow);
                    ldsm4t(bwh[4], bwh[5], bwh[6], bwh[7], b0 + 4 * MAT + brow + 32);
                    ldsm4t(bwl[0], bwl[1], bwl[2], bwl[3], b0 + 5 * MAT + brow);
                    ldsm4t(bwl[4], bwl[5], bwl[6], bwl[7], b0 + 5 * MAT + brow + 32);
                    ldsm4t(buh[0], buh[1], buh[2], buh[3], b0 + 6 * MAT + brow);
                    ldsm4t(buh[4], buh[5], buh[6], buh[7], b0 + 6 * MAT + brow + 32);
                    ldsm4t(bul[0], bul[1], bul[2], bul[3], b0 + 7 * MAT + brow);
                    ldsm4t(bul[4], bul[5], bul[6], bul[7], b0 + 7 * MAT + brow + 32);
#pragma unroll
                    for (int ni = 0; ni < 4; ++ni) {
                        mma_bf16(acc[ni], fxh, bwh + ni * 2);
                        mma_bf16(acc[ni], fxh, bwl + ni * 2);
                        mma_bf16(acc[ni], fxl, bwh + ni * 2);
                        mma_bf16(acc[ni], fhh, buh + ni * 2);
                        mma_bf16(acc[ni], fhh, bul + ni * 2);
                        mma_bf16(acc[ni], fhl, buh + ni * 2);
                    }
                }
                BARA(4 + ch % 3);
            }

            // in-register gates (lane pair exchanges gate halves via shfl)
#pragma unroll
            for (int ni = 0; ni < 4; ++ni) {
                float e0 = __shfl_xor_sync(0xFFFFFFFF, acc[ni][0], 1);
                float e1 = __shfl_xor_sync(0xFFFFFFFF, acc[ni][1], 1);
                float e2 = __shfl_xor_sync(0xFFFFFFFF, acc[ni][2], 1);
                float e3 = __shfl_xor_sync(0xFFFFFFFF, acc[ni][3], 1);
                float zi, zf, zg, zo;
                if ((p & 1) == 0) { zi = acc[ni][0]; zf = acc[ni][1]; zg = e0; zo = e1; }
                else              { zi = e2;         zf = e3;         zg = acc[ni][2]; zo = acc[ni][3]; }
                zi += breg[ni][0]; zf += breg[ni][1]; zg += breg[ni][2]; zo += breg[ni][3];
                float c = sigf(zf) * cst[ni] + sigf(zi) * tanhf(zg);
                cst[ni] = c;
                float h = sigf(zo) * tanhf(c);
                int col = colv[ni];
                float val = h + xres[ni];
                __nv_bfloat16 hb = __float2bfloat16_rn(h);
                g_hh[g][t & 1][rowb * Hh + col] = hb;
                g_hl[g][t & 1][rowb * Hh + col] = __float2bfloat16_rn(h - __bfloat162float(hb));
                if (g < 3) {
                    size_t idx = ((size_t)t * Bx + rowb) * Hh + col;
                    __nv_bfloat16 vb = __float2bfloat16_rn(val);
                    g_xh[g + 1][idx] = vb;
                    g_xl[g + 1][idx] = __float2bfloat16_rn(val - __bfloat162float(vb));
                } else {
                    out[(size_t)rowb * Tt * Hh + (size_t)t * Hh + col] = val;
                }
                if (g == 0 && t == Tt - 1) g_firsth[rowb * Hh + col] = h;
            }
        }

        __syncthreads();
        if (tid == 0) {
            asm volatile("fence.acq_rel.gpu;" ::: "memory");
            atomicAdd(&g_cnt[g], 1u);
        }
    }
}

// ---------------- launch ----------------
extern "C" void kernel_launch(void* const* d_in, const int* in_sizes, int n_in,
                              void* d_out, int out_size) {
    const float* x    = (const float*)d_in[0];
    const float* W    = (const float*)d_in[1];
    const float* U    = (const float*)d_in[2];
    const float* bias = (const float*)d_in[3];
    float* out = (float*)d_out;

    cudaFuncSetAttribute(k_wave, cudaFuncAttributeMaxDynamicSharedMemorySize, SM_TOTAL);

    k_init<<<128, 256>>>();
    k_prep<<<dim3(Tt, Bx), 64>>>(x);
    k_splitWU<<<8192, 256>>>(W, U);
    k_wave<<<128, NTHR, SM_TOTAL>>>(bias, out);
    k_states<<<Bx, 128>>>(out);
}

// round 17
// speedup vs baseline: 1.5553x; 1.5553x over previous
#include <cuda_runtime.h>
#include <cuda_bf16.h>
#include <math.h>

typedef unsigned int u32;
typedef unsigned long long u64;

#define Bx 64
#define Tt 512
#define Hh 512
#define Gg 2048
#define TBH (Tt * Bx * Hh)
#define MAT 9216                 // one 64x64 bf16 matrix, 144B row stride
#define BUFB (8 * MAT)           // 8 matrices per chunk buffer (73728 B)
#define SM_TOTAL (3 * BUFB)      // 221184 B (3-stage ring)
#define NTHR 320                 // 8 consumer warps + 2 producer warps

// ---------------- device scratch ----------------
__device__ __nv_bfloat16 g_xh[4][TBH], g_xl[4][TBH];      // layer-input splits [t][b][k]
__device__ __nv_bfloat16 g_Wh[4][Hh * Gg], g_Wl[4][Hh * Gg];  // gate-interleaved cols
__device__ __nv_bfloat16 g_Uh[4][Hh * Gg], g_Ul[4][Hh * Gg];  // (col' = j*64 + nn*4 + g)
__device__ __nv_bfloat16 g_hh[4][2][Bx * Hh], g_hl[4][2][Bx * Hh];  // h splits, dbl-buffered
__device__ float g_firsth[Bx * Hh];
__device__ unsigned g_cnt[4];                              // per-group monotonic counters

// ---------------- helpers ----------------
__device__ __forceinline__ u32 smem_u32(const void* p) {
    u32 a;
    asm("{ .reg .u64 t; cvta.to.shared.u64 t, %1; cvt.u32.u64 %0, t; }" : "=r"(a) : "l"(p));
    return a;
}
__device__ __forceinline__ void ldsm4(u32& r0, u32& r1, u32& r2, u32& r3, u32 a) {
    asm volatile("ldmatrix.sync.aligned.m8n8.x4.shared.b16 {%0,%1,%2,%3}, [%4];"
                 : "=r"(r0), "=r"(r1), "=r"(r2), "=r"(r3) : "r"(a));
}
__device__ __forceinline__ void ldsm4t(u32& r0, u32& r1, u32& r2, u32& r3, u32 a) {
    asm volatile("ldmatrix.sync.aligned.m8n8.x4.trans.shared.b16 {%0,%1,%2,%3}, [%4];"
                 : "=r"(r0), "=r"(r1), "=r"(r2), "=r"(r3) : "r"(a));
}
__device__ __forceinline__ void mma_bf16(float* c, const u32* a, const u32* b) {
    asm volatile("mma.sync.aligned.m16n8k16.row.col.f32.bf16.bf16.f32 "
                 "{%0,%1,%2,%3}, {%4,%5,%6,%7}, {%8,%9}, {%0,%1,%2,%3};"
                 : "+f"(c[0]), "+f"(c[1]), "+f"(c[2]), "+f"(c[3])
                 : "r"(a[0]), "r"(a[1]), "r"(a[2]), "r"(a[3]), "r"(b[0]), "r"(b[1]));
}
#define CP16(dst, src) asm volatile("cp.async.cg.shared.global [%0], [%1], 16;" :: "r"(dst), "l"(src) : "memory")
#define CPCOMMIT()     asm volatile("cp.async.commit_group;" ::: "memory")
#define CPWAIT0()      asm volatile("cp.async.wait_group 0;" ::: "memory")
#define CPWAIT1()      asm volatile("cp.async.wait_group 1;" ::: "memory")
#define CPWAIT2()      asm volatile("cp.async.wait_group 2;" ::: "memory")
#define BARS(id)       asm volatile("bar.sync %0, %1;"   :: "r"(id), "n"(NTHR) : "memory")
#define BARA(id)       asm volatile("bar.arrive %0, %1;" :: "r"(id), "n"(NTHR) : "memory")

__device__ __forceinline__ float sigf(float x) { return 1.f / (1.f + __expf(-x)); }
__device__ __forceinline__ u32 ld_rel(const unsigned* p) {
    u32 v;
    asm volatile("ld.relaxed.gpu.global.u32 %0, [%1];" : "=r"(v) : "l"(p));
    return v;
}
__device__ __forceinline__ void split8(float4 f0, float4 f1, uint4& hv, uint4& lv) {
    float f[8] = {f0.x, f0.y, f0.z, f0.w, f1.x, f1.y, f1.z, f1.w};
    __nv_bfloat16 h[8], l[8];
#pragma unroll
    for (int i = 0; i < 8; ++i) {
        h[i] = __float2bfloat16_rn(f[i]);
        l[i] = __float2bfloat16_rn(f[i] - __bfloat162float(h[i]));
    }
    hv = *reinterpret_cast<uint4*>(h);
    lv = *reinterpret_cast<uint4*>(l);
}

// ---------------- prep / init / states ----------------
__global__ void k_init() {
    if (blockIdx.x == 0 && threadIdx.x < 4) g_cnt[threadIdx.x] = 0u;
    int idx = blockIdx.x * 256 + threadIdx.x;  // 32768 uint4 per array
    ((uint4*)g_hh)[idx] = make_uint4(0, 0, 0, 0);
    ((uint4*)g_hl)[idx] = make_uint4(0, 0, 0, 0);
}
__global__ void k_prep(const float* __restrict__ x) {
    int t = blockIdx.x, b = blockIdx.y, i = threadIdx.x;  // 64 threads, 8 cols each
    const float* src = x + ((size_t)b * Tt + t) * Hh + i * 8;
    float4 f0 = __ldg((const float4*)src), f1 = __ldg((const float4*)(src + 4));
    uint4 hv, lv;
    split8(f0, f1, hv, lv);
    size_t o = ((size_t)t * Bx + b) * Hh + i * 8;
    *(uint4*)(&g_xh[0][o]) = hv;
    *(uint4*)(&g_xl[0][o]) = lv;
}
// split W,U for all 4 layers with gate-interleaved columns:
// dst col' = j*64 + nn*4 + g   <- src col g*512 + j*16 + nn
__global__ void k_splitWU(const float* __restrict__ W, const float* __restrict__ U) {
    int bid = blockIdx.x;
    const float* src = (bid < 4096) ? W : U;
    __nv_bfloat16* dh = (bid < 4096) ? &g_Wh[0][0] : &g_Uh[0][0];
    __nv_bfloat16* dl = (bid < 4096) ? &g_Wl[0][0] : &g_Ul[0][0];
    size_t base = ((size_t)(bid & 4095) * 256 + threadIdx.x) * 4;
#pragma unroll
    for (int q = 0; q < 4; ++q) {
        size_t e = base + q;                 // linear over [layer][k][colp]
        int colp = (int)(e & 2047);
        size_t lk = e >> 11;                 // layer*512 + k
        int j = colp >> 6, r = colp & 63;
        int nn = r >> 2, g = r & 3;
        float f = __ldg(src + lk * 2048 + g * 512 + j * 16 + nn);
        __nv_bfloat16 hi = __float2bfloat16_rn(f);
        dh[e] = hi;
        dl[e] = __float2bfloat16_rn(f - __bfloat162float(hi));
    }
}
__global__ void k_states(float* __restrict__ out) {
    int b = blockIdx.x;
    float4 v = ((const float4*)(g_firsth + (size_t)b * Hh))[threadIdx.x];
    size_t base = (size_t)Bx * Tt * Hh;
#pragma unroll
    for (int l = 0; l < 4; ++l)
        ((float4*)(out + base + ((size_t)l * Bx + b) * Hh))[threadIdx.x] = v;
}

// ---------------- wavefront-pipelined fused LSTM (warp-specialized) ----------------
// 128 CTAs = 4 layer-groups x 32. 320 threads: warps 0-7 consumers (4m x 2n),
// warps 8-9 producers. R13 structure (tid0 spin + two CTA barriers per step,
// proven correct) + weight staging of chunks 0/1 hoisted into the spin window
// (weights are flag-free; slots 0/1 provably free after the step-end barrier).
__global__ void __launch_bounds__(NTHR) k_wave(const float* __restrict__ bias,
                                               float* __restrict__ out) {
    extern __shared__ __align__(128) unsigned char sm[];
    u32 sb = smem_u32(sm);
    const int tid = threadIdx.x, w = tid >> 5, lane = tid & 31;
    const int g = blockIdx.x >> 5, j = blockIdx.x & 31;
    const bool consumer = (w < 8);
    const int mw = (w & 3) * 16, nw = ((w >> 2) & 1) * 32;  // consumers: 4m x 2n
    const int p = lane & 3;

    // consumer cell geometry: ni 0..3
    const int rowb = mw + (lane >> 2) + ((p & 1) ? 8 : 0);
    int colv[4];
    float breg[4][4];
#pragma unroll
    for (int ni = 0; ni < 4; ++ni) {
        int nn = (nw >> 2) + ni * 2 + (p >> 1);
        colv[ni] = j * 16 + nn;
#pragma unroll
        for (int q = 0; q < 4; ++q)
            breg[ni][q] = __ldg(bias + g * Gg + q * 512 + colv[ni]);
    }

    const __nv_bfloat16* wh = g_Wh[g];
    const __nv_bfloat16* wl = g_Wl[g];
    const __nv_bfloat16* uh = g_Uh[g];
    const __nv_bfloat16* ul = g_Ul[g];

    const int pt = tid - 256;  // producer linear id 0..63
    float cst[4] = {0.f, 0.f, 0.f, 0.f};

    for (int t = 0; t < Tt; ++t) {
        const __nv_bfloat16* axh = g_xh[g] + (size_t)t * Bx * Hh;
        const __nv_bfloat16* axl = g_xl[g] + (size_t)t * Bx * Hh;
        const __nv_bfloat16* ahh = g_hh[g][(t & 1) ^ 1];
        const __nv_bfloat16* ahl = g_hl[g][(t & 1) ^ 1];

        // producer lambdas
        auto stageW = [&](int ch) {
            u32 base = sb + (ch % 3) * BUFB;
            int co = ch * 64;
#pragma unroll
            for (int it = 0; it < 8; ++it) {
                int x = it * 64 + pt;
                int r = x >> 3, c = x & 7;
                u32 ad = r * 144 + c * 16;
                size_t bso = (size_t)(co + r) * Gg + j * 64 + c * 8;
                CP16(base + 4 * MAT + ad, wh + bso);
                CP16(base + 5 * MAT + ad, wl + bso);
                CP16(base + 6 * MAT + ad, uh + bso);
                CP16(base + 7 * MAT + ad, ul + bso);
            }
        };
        auto stageXH = [&](int ch) {
            u32 base = sb + (ch % 3) * BUFB;
            int co = ch * 64;
#pragma unroll
            for (int it = 0; it < 8; ++it) {
                int x = it * 64 + pt;
                int r = x >> 3, c = x & 7;
                size_t aso = (size_t)r * Hh + co + c * 8;
                u32 ad = r * 144 + c * 16;
                CP16(base + ad, axh + aso);
                CP16(base + MAT + ad, axl + aso);
                CP16(base + 2 * MAT + ad, ahh + aso);
                CP16(base + 3 * MAT + ad, ahl + aso);
            }
        };
        auto stage = [&](int ch) { stageW(ch); stageXH(ch); };

        // step boundary: producers pre-stage weights of chunks 0/1 (flag-free)
        // while tid0 spins on the inter-step / inter-group flags.
        if (!consumer) {
            if (t > 0) BARS(4 + 0);   // empty[0]: arrival posted at (t-1, ch=6)
            stageW(0);
            if (t > 0) BARS(4 + 1);   // empty[1]: arrival posted at (t-1, ch=7)
            stageW(1);
        } else if (tid == 0) {
            u32 tg = 32u * (u32)t;
            while (ld_rel(&g_cnt[g]) < tg) { }
            if (g > 0) {
                u32 tg2 = 32u * (u32)(t + 1);
                while (ld_rel(&g_cnt[g - 1]) < tg2) { }
            }
            asm volatile("fence.acq_rel.gpu;" ::: "memory");
        }
        __syncthreads();

        if (!consumer) {
            // ---------------- producer path ----------------
            stageXH(0); CPCOMMIT();   // group0 = {W0, W1, XH0}
            stageXH(1); CPCOMMIT();   // group1 = {XH1}
#pragma unroll 1
            for (int ch = 0; ch < 8; ++ch) {
                int nb = ch + 2;
                if (nb < 8) {
                    if (t > 0 || nb > 2) BARS(4 + nb % 3);
                    stage(nb); CPCOMMIT();
                    CPWAIT2();
                } else if (ch == 6) {
                    CPWAIT1();
                } else {
                    CPWAIT0();
                }
                BARA(1 + ch % 3);
            }
        } else {
            // ---------------- consumer path ----------------
            float xres[4] = {0.f, 0.f, 0.f, 0.f};
            if (g > 0) {
#pragma unroll
                for (int ni = 0; ni < 4; ++ni)
                    xres[ni] = __bfloat162float(__ldg(&axh[rowb * Hh + colv[ni]])) +
                               __bfloat162float(__ldg(&axl[rowb * Hh + colv[ni]]));
            }
            float acc[4][4];
#pragma unroll
            for (int a = 0; a < 4; ++a)
#pragma unroll
                for (int q = 0; q < 4; ++q) acc[a][q] = 0.f;

#pragma unroll 1
            for (int ch = 0; ch < 8; ++ch) {
                BARS(1 + ch % 3);
                u32 b0 = sb + (ch % 3) * BUFB;
#pragma unroll
                for (int kk = 0; kk < 4; ++kk) {
                    int k0 = kk * 16;
                    u32 arow = (mw + (lane & 15)) * 144 + (k0 + ((lane >> 4) << 3)) * 2;
                    u32 fxh[4], fxl[4], fhh[4], fhl[4];
                    ldsm4(fxh[0], fxh[1], fxh[2], fxh[3], b0 + arow);
                    ldsm4(fxl[0], fxl[1], fxl[2], fxl[3], b0 + MAT + arow);
                    ldsm4(fhh[0], fhh[1], fhh[2], fhh[3], b0 + 2 * MAT + arow);
                    ldsm4(fhl[0], fhl[1], fhl[2], fhl[3], b0 + 3 * MAT + arow);
                    u32 brow = (k0 + (lane & 7) + ((lane & 8) ? 8 : 0)) * 144 +
                               (nw + ((lane & 16) ? 8 : 0)) * 2;
                    u32 bwh[8], bwl[8], buh[8], bul[8];
                    ldsm4t(bwh[0], bwh[1], bwh[2], bwh[3], b0 + 4 * MAT + brow);
                    ldsm4t(bwh[4], bwh[5], bwh[6], bwh[7], b0 + 4 * MAT + brow + 32);
                    ldsm4t(bwl[0], bwl[1], bwl[2], bwl[3], b0 + 5 * MAT + brow);
                    ldsm4t(bwl[4], bwl[5], bwl[6], bwl[7], b0 + 5 * MAT + brow + 32);
                    ldsm4t(buh[0], buh[1], buh[2], buh[3], b0 + 6 * MAT + brow);
                    ldsm4t(buh[4], buh[5], buh[6], buh[7], b0 + 6 * MAT + brow + 32);
                    ldsm4t(bul[0], bul[1], bul[2], bul[3], b0 + 7 * MAT + brow);
                    ldsm4t(bul[4], bul[5], bul[6], bul[7], b0 + 7 * MAT + brow + 32);
#pragma unroll
                    for (int ni = 0; ni < 4; ++ni) {
                        mma_bf16(acc[ni], fxh, bwh + ni * 2);
                        mma_bf16(acc[ni], fxh, bwl + ni * 2);
                        mma_bf16(acc[ni], fxl, bwh + ni * 2);
                        mma_bf16(acc[ni], fhh, buh + ni * 2);
                        mma_bf16(acc[ni], fhh, bul + ni * 2);
                        mma_bf16(acc[ni], fhl, buh + ni * 2);
                    }
                }
                BARA(4 + ch % 3);
            }

            // in-register gates (lane pair exchanges gate halves via shfl)
#pragma unroll
            for (int ni = 0; ni < 4; ++ni) {
                float e0 = __shfl_xor_sync(0xFFFFFFFF, acc[ni][0], 1);
                float e1 = __shfl_xor_sync(0xFFFFFFFF, acc[ni][1], 1);
                float e2 = __shfl_xor_sync(0xFFFFFFFF, acc[ni][2], 1);
                float e3 = __shfl_xor_sync(0xFFFFFFFF, acc[ni][3], 1);
                float zi, zf, zg, zo;
                if ((p & 1) == 0) { zi = acc[ni][0]; zf = acc[ni][1]; zg = e0; zo = e1; }
                else              { zi = e2;         zf = e3;         zg = acc[ni][2]; zo = acc[ni][3]; }
                zi += breg[ni][0]; zf += breg[ni][1]; zg += breg[ni][2]; zo += breg[ni][3];
                float c = sigf(zf) * cst[ni] + sigf(zi) * tanhf(zg);
                cst[ni] = c;
                float h = sigf(zo) * tanhf(c);
                int col = colv[ni];
                float val = h + xres[ni];
                __nv_bfloat16 hb = __float2bfloat16_rn(h);
                g_hh[g][t & 1][rowb * Hh + col] = hb;
                g_hl[g][t & 1][rowb * Hh + col] = __float2bfloat16_rn(h - __bfloat162float(hb));
                if (g < 3) {
                    size_t idx = ((size_t)t * Bx + rowb) * Hh + col;
                    __nv_bfloat16 vb = __float2bfloat16_rn(val);
                    g_xh[g + 1][idx] = vb;
                    g_xl[g + 1][idx] = __float2bfloat16_rn(val - __bfloat162float(vb));
                } else {
                    out[(size_t)rowb * Tt * Hh + (size_t)t * Hh + col] = val;
                }
                if (g == 0 && t == Tt - 1) g_firsth[rowb * Hh + col] = h;
            }
        }

        __syncthreads();
        if (tid == 0) {
            asm volatile("fence.acq_rel.gpu;" ::: "memory");
            atomicAdd(&g_cnt[g], 1u);
        }
    }
}

// ---------------- launch ----------------
extern "C" void kernel_launch(void* const* d_in, const int* in_sizes, int n_in,
                              void* d_out, int out_size) {
    const float* x    = (const float*)d_in[0];
    const float* W    = (const float*)d_in[1];
    const float* U    = (const float*)d_in[2];
    const float* bias = (const float*)d_in[3];
    float* out = (float*)d_out;

    cudaFuncSetAttribute(k_wave, cudaFuncAttributeMaxDynamicSharedMemorySize, SM_TOTAL);

    k_init<<<128, 256>>>();
    k_prep<<<dim3(Tt, Bx), 64>>>(x);
    k_splitWU<<<8192, 256>>>(W, U);
    k_wave<<<128, NTHR, SM_TOTAL>>>(bias, out);
    k_states<<<Bx, 128>>>(out);
}